// round 16
// baseline (speedup 1.0000x reference)
#include <cuda_runtime.h>
#include <cuda_fp16.h>
#include <math.h>
#include <stdint.h>

#define BATCH 2
#define SEQ   2048
#define HID   2048
#define NH    16
#define HD    128
#define MROWS (BATCH*SEQ)   // 4096

// -------- scratch (static device globals, all half) ------------------------
__device__ __half g_qh[BATCH*NH*SEQ*HD];   // rope applied
__device__ __half g_kh[BATCH*NH*SEQ*HD];
__device__ __half g_vh[BATCH*NH*SEQ*HD];
__device__ __half g_atth[MROWS*HID];
__device__ __half g_xh[MROWS*HID];
__device__ __half g_wqT[HID*HID];          // W^T [N][K]
__device__ __half g_wkT[HID*HID];
__device__ __half g_wvT[HID*HID];
__device__ __half g_woT[HID*HID];
__device__ float  g_sin[SEQ*HD];
__device__ float  g_cos[SEQ*HD];

// -------- helpers ----------------------------------------------------------
__device__ __forceinline__ uint32_t smem_u32(const void* p) {
    uint32_t a;
    asm("{ .reg .u64 t; cvta.to.shared.u64 t, %1; cvt.u32.u64 %0, t; }"
        : "=r"(a) : "l"(p));
    return a;
}

__device__ __forceinline__ void cpa16(uint32_t dst, const void* src) {
    asm volatile(
        "{ .reg .u64 ga; cvta.to.global.u64 ga, %1;"
        "  cp.async.cg.shared.global [%0], [ga], 16; }"
        :: "r"(dst), "l"(src) : "memory");
}
__device__ __forceinline__ void cpa_commit() {
    asm volatile("cp.async.commit_group;" ::: "memory");
}
__device__ __forceinline__ void cpa_wait1() {
    asm volatile("cp.async.wait_group 1;" ::: "memory");
}

__device__ __forceinline__ void mma_f16(float* d, const unsigned* a, const unsigned* b) {
    asm volatile(
        "mma.sync.aligned.m16n8k16.row.col.f32.f16.f16.f32 "
        "{%0,%1,%2,%3}, {%4,%5,%6,%7}, {%8,%9}, {%0,%1,%2,%3};"
        : "+f"(d[0]), "+f"(d[1]), "+f"(d[2]), "+f"(d[3])
        : "r"(a[0]), "r"(a[1]), "r"(a[2]), "r"(a[3]), "r"(b[0]), "r"(b[1]));
}

__device__ __forceinline__ void ldsm4(unsigned* r, uint32_t addr) {
    asm volatile("ldmatrix.sync.aligned.m8n8.x4.shared.b16 {%0,%1,%2,%3}, [%4];"
        : "=r"(r[0]), "=r"(r[1]), "=r"(r[2]), "=r"(r[3]) : "r"(addr));
}
__device__ __forceinline__ void ldsm4t(unsigned* r, uint32_t addr) {
    asm volatile("ldmatrix.sync.aligned.m8n8.x4.trans.shared.b16 {%0,%1,%2,%3}, [%4];"
        : "=r"(r[0]), "=r"(r[1]), "=r"(r[2]), "=r"(r[3]) : "r"(addr));
}

// -------- RoPE table -------------------------------------------------------
__global__ void rope_table_kernel() {
    int idx = blockIdx.x * blockDim.x + threadIdx.x;
    if (idx >= SEQ*HD) return;
    int s = idx >> 7;
    int d = idx & 127;
    int j = d >> 1;
    float inv = (float)exp(-2.0 * (double)j / 128.0 * log(10000.0));
    float ang = (float)s * inv;
    g_sin[idx] = (float)sin((double)ang);
    g_cos[idx] = (float)cos((double)ang);
}

// -------- X -> half --------------------------------------------------------
__global__ void cvt_x_kernel(const float* __restrict__ X) {
    int i = (blockIdx.x * blockDim.x + threadIdx.x) * 8;
    float4 v0 = *(const float4*)(X + i);
    float4 v1 = *(const float4*)(X + i + 4);
    __half2 h[4];
    h[0] = __floats2half2_rn(v0.x, v0.y);
    h[1] = __floats2half2_rn(v0.z, v0.w);
    h[2] = __floats2half2_rn(v1.x, v1.y);
    h[3] = __floats2half2_rn(v1.z, v1.w);
    *(uint4*)(g_xh + i) = *(uint4*)h;
}

// -------- W [K][N] -> W^T [N][K] half, all 4 weights -----------------------
__global__ void wtrans_kernel(const float* __restrict__ Wq, const float* __restrict__ Wk,
                              const float* __restrict__ Wv, const float* __restrict__ Wo) {
    __shared__ float tile[32][33];
    const float* src; __half* dst;
    if (blockIdx.z == 0)      { src = Wq; dst = g_wqT; }
    else if (blockIdx.z == 1) { src = Wk; dst = g_wkT; }
    else if (blockIdx.z == 2) { src = Wv; dst = g_wvT; }
    else                      { src = Wo; dst = g_woT; }
    const int bx = blockIdx.x * 32;   // N
    const int by = blockIdx.y * 32;   // K
    const int tx = threadIdx.x, ty = threadIdx.y;
    #pragma unroll
    for (int j = 0; j < 32; j += 8)
        tile[ty + j][tx] = src[(size_t)(by + ty + j) * HID + bx + tx];
    __syncthreads();
    #pragma unroll
    for (int j = 0; j < 32; j += 8)
        dst[(size_t)(bx + ty + j) * HID + by + tx] = __float2half(tile[tx][ty + j]);
}

// -------- FP16 mma GEMM: C = A[M,K]@Bt[N,K]^T + bias -----------------------
// BM=256, BN=128, BK=64. 8 warps (4m x 2n), warp tile 64x64. 1 CTA/SM.
// 3-stage cp.async ring, fragment double-buffering.
#define AS_STRIDE 36                       // words per row (32 data + 4 pad)
#define A_WORDS (256*AS_STRIDE)            // 9216
#define B_WORDS (128*AS_STRIDE)            // 4608
#define STAGE_WORDS (A_WORDS + B_WORDS)    // 13824
#define STAGE_BYTES (STAGE_WORDS*4)        // 55296
#define GSMEM_BYTES (3*STAGE_BYTES)        // 165888

__device__ __forceinline__ void gemm_body_h(
    const int mode,
    const __half* __restrict__ A, const __half* __restrict__ Bt,
    const float* __restrict__ bias, void* __restrict__ Cv,
    unsigned* smem, const int N, const int K)
{
    const uint32_t sbase = smem_u32(smem);
    const int t = threadIdx.x, wid = t >> 5, lane = t & 31;
    const int g = lane >> 2, c = lane & 3;
    const int wrow = wid >> 1, wcol = wid & 1;     // 4m x 2n
    const int m0 = blockIdx.y * 256, n0 = blockIdx.x * 128;

    const int lm15  = lane & 15;
    const int lmsel = (lane & 16) ? 4 : 0;
    const int brow  = (lane & 7) + ((lane & 16) ? 8 : 0);
    const int bsel  = (lane & 8) ? 4 : 0;

    // loader: lr = t>>3 (0..31), lq = t&7; A rows lr+32s (s 0..7), B rows lr+32s (s 0..3)
    const int lr = t >> 3, lq = t & 7;
    const __half* aP = A  + (size_t)(m0 + lr) * K + lq * 8;
    const __half* bP = Bt + (size_t)(n0 + lr) * K + lq * 8;
    const uint32_t aO = (lr * AS_STRIDE + lq * 4) * 4;
    const uint32_t bO = aO + A_WORDS * 4;
    const uint32_t chunkStride = 32 * AS_STRIDE * 4;

    float acc[4][8][4];
    #pragma unroll
    for (int i = 0; i < 4; i++)
        #pragma unroll
        for (int j = 0; j < 8; j++)
            #pragma unroll
            for (int r = 0; r < 4; r++) acc[i][j][r] = 0.0f;

    const int NIT = K >> 6;   // 32

    #pragma unroll
    for (int p = 0; p < 2; p++) {
        uint32_t sb = sbase + p * STAGE_BYTES;
        #pragma unroll
        for (int s = 0; s < 8; s++)
            cpa16(sb + aO + s * chunkStride, aP + p * 64 + (size_t)s * 32 * K);
        #pragma unroll
        for (int s = 0; s < 4; s++)
            cpa16(sb + bO + s * chunkStride, bP + p * 64 + (size_t)s * 32 * K);
        cpa_commit();
    }

    int rslot = 0, wslot = 2;
    for (int i = 0; i < NIT; i++) {
        cpa_wait1();
        __syncthreads();

        if (i + 2 < NIT) {
            uint32_t sb = sbase + wslot * STAGE_BYTES;
            #pragma unroll
            for (int s = 0; s < 8; s++)
                cpa16(sb + aO + s * chunkStride, aP + (i + 2) * 64 + (size_t)s * 32 * K);
            #pragma unroll
            for (int s = 0; s < 4; s++)
                cpa16(sb + bO + s * chunkStride, bP + (i + 2) * 64 + (size_t)s * 32 * K);
        }
        cpa_commit();
        if (++wslot == 3) wslot = 0;

        const uint32_t sA = sbase + rslot * STAGE_BYTES;
        const uint32_t sB = sA + A_WORDS * 4;
        if (++rslot == 3) rslot = 0;

        // fragment double-buffer over 4 ksteps of k16
        unsigned af[2][4][4], bf[2][4][4];
        #pragma unroll
        for (int mt = 0; mt < 4; mt++)
            ldsm4(af[0][mt], sA + ((wrow*64 + mt*16 + lm15) * AS_STRIDE + lmsel) * 4);
        #pragma unroll
        for (int np = 0; np < 4; np++)
            ldsm4(bf[0][np], sB + ((wcol*64 + np*16 + brow) * AS_STRIDE + bsel) * 4);

        #pragma unroll
        for (int ks = 0; ks < 4; ks++) {
            const int cur = ks & 1, nxt = cur ^ 1;
            if (ks < 3) {
                const int ko = (ks + 1) * 8;
                #pragma unroll
                for (int mt = 0; mt < 4; mt++)
                    ldsm4(af[nxt][mt], sA + ((wrow*64 + mt*16 + lm15) * AS_STRIDE + ko + lmsel) * 4);
                #pragma unroll
                for (int np = 0; np < 4; np++)
                    ldsm4(bf[nxt][np], sB + ((wcol*64 + np*16 + brow) * AS_STRIDE + ko + bsel) * 4);
            }
            #pragma unroll
            for (int np = 0; np < 4; np++)
                #pragma unroll
                for (int mt = 0; mt < 4; mt++) {
                    mma_f16(acc[mt][np*2 + 0], af[cur][mt], &bf[cur][np][0]);
                    mma_f16(acc[mt][np*2 + 1], af[cur][mt], &bf[cur][np][2]);
                }
        }
    }

    // Epilogue
    #pragma unroll
    for (int mt = 0; mt < 4; mt++) {
        #pragma unroll
        for (int nt = 0; nt < 8; nt++) {
            const int col = n0 + wcol * 64 + nt * 8 + 2 * c;
            #pragma unroll
            for (int half_ = 0; half_ < 2; half_++) {
                const int row = m0 + wrow * 64 + mt * 16 + g + half_ * 8;
                float v0 = acc[mt][nt][half_ * 2 + 0] + bias[col];
                float v1 = acc[mt][nt][half_ * 2 + 1] + bias[col + 1];
                if (mode == 0) {
                    float* C = (float*)Cv;
                    float2 o = make_float2(v0, v1);
                    *(float2*)(C + (size_t)row * N + col) = o;
                } else {
                    const int b = row >> 11;
                    const int s = row & (SEQ - 1);
                    const int h = col >> 7;
                    const int d = col & 127;
                    if (mode == 1) {
                        float sn = g_sin[s * HD + d];
                        float cs = g_cos[s * HD + d];
                        float o0 = v0 * cs - v1 * sn;
                        float o1 = v1 * cs + v0 * sn;
                        v0 = o0; v1 = o1;
                    }
                    size_t oidx = ((size_t)((b * NH + h) * SEQ + s)) * HD + d;
                    __half2 hv = __floats2half2_rn(v0, v1);
                    *(__half2*)((__half*)Cv + oidx) = hv;
                }
            }
        }
    }
}

__global__ __launch_bounds__(256, 1) void qkv_gemm(
    const float* __restrict__ bq, const float* __restrict__ bk,
    const float* __restrict__ bv)
{
    extern __shared__ unsigned smem[];
    const __half* Bt; const float* bias; __half* C; int mode;
    if (blockIdx.z == 0)      { Bt = g_wqT; bias = bq; C = g_qh; mode = 1; }
    else if (blockIdx.z == 1) { Bt = g_wkT; bias = bk; C = g_kh; mode = 1; }
    else                      { Bt = g_wvT; bias = bv; C = g_vh; mode = 2; }
    gemm_body_h(mode, g_xh, Bt, bias, C, smem, HID, HID);
}

__global__ __launch_bounds__(256, 1) void gemm_o(
    const float* __restrict__ bo, float* __restrict__ out)
{
    extern __shared__ unsigned smem[];
    gemm_body_h(0, g_atth, g_woT, bo, out, smem, HID, HID);
}

// -------- Flash attention fp16, FA2 layout: Br=128, Bc=64, 256 thr ---------
// (unchanged — passing, register softmax)
#define ATQ  0                       // 8192 words
#define ATK  8192                    // 2 x 4096
#define ATV  16384                   // 2 x 4096
#define ATT_TOT 24576
#define ASMEM_BYTES (ATT_TOT * 4)    // 98304

__global__ __launch_bounds__(256, 2) void attn_kernel() {
    extern __shared__ unsigned sm[];
    const uint32_t sbase = smem_u32(sm);

    const int t = threadIdx.x, wid = t >> 5, lane = t & 31;
    const int g = lane >> 2, c = lane & 3;

    const int lm15  = lane & 15;
    const int lmsel = (lane & 16) ? 4 : 0;
    const int krow  = (lane & 7) + ((lane & 16) ? 8 : 0);
    const int ksel  = (lane & 8) ? 4 : 0;
    const int vsel  = (lane & 16) ? 4 : 0;
    const int lsw   = (lane & 7) << 2;

    const int q0 = blockIdx.x * 128;
    const int h  = blockIdx.y;
    const int b  = blockIdx.z;
    const size_t bh_off = (size_t)(b * NH + h) * SEQ * HD;
    const __half* qg = g_qh + bh_off;
    const __half* kg = g_kh + bh_off;
    const __half* vg = g_vh + bh_off;

    #pragma unroll
    for (int p = 0; p < 8; p++) {
        int lin = p * 256 + t;
        int r = lin >> 4, c4 = lin & 15;
        uint32_t swz = ((c4 * 4) ^ ((r & 7) << 2));
        cpa16(sbase + (ATQ + r * 64 + swz) * 4, qg + (size_t)(q0 + r) * HD + c4 * 8);
    }
    #pragma unroll
    for (int p = 0; p < 4; p++) {
        int lin = p * 256 + t;
        int r = lin >> 4, c4 = lin & 15;
        uint32_t swz = ((c4 * 4) ^ ((r & 7) << 2));
        cpa16(sbase + (ATK + r * 64 + swz) * 4, kg + (size_t)r * HD + c4 * 8);
        cpa16(sbase + (ATV + r * 64 + swz) * 4, vg + (size_t)r * HD + c4 * 8);
    }
    cpa_commit();
    #pragma unroll
    for (int p = 0; p < 4; p++) {
        int lin = p * 256 + t;
        int r = lin >> 4, c4 = lin & 15;
        uint32_t swz = ((c4 * 4) ^ ((r & 7) << 2));
        cpa16(sbase + (ATK + 4096 + r * 64 + swz) * 4, kg + (size_t)(64 + r) * HD + c4 * 8);
        cpa16(sbase + (ATV + 4096 + r * 64 + swz) * 4, vg + (size_t)(64 + r) * HD + c4 * 8);
    }
    cpa_commit();

    float m0 = -INFINITY, m1 = -INFINITY;
    float l0 = 0.0f, l1 = 0.0f;

    float oacc[16][4];
    #pragma unroll
    for (int i = 0; i < 16; i++)
        #pragma unroll
        for (int r = 0; r < 4; r++) oacc[i][r] = 0.0f;

    const float scale = 0.08838834764831845f;
    const uint32_t qrow_base = sbase + (ATQ + (wid * 16 + lm15) * 64) * 4;

    for (int it = 0; it < SEQ / 64; it++) {
        cpa_wait1();
        __syncthreads();
        const uint32_t kbb = sbase + (ATK + (it & 1) * 4096) * 4;
        const uint32_t vbb = sbase + (ATV + (it & 1) * 4096) * 4;

        float sacc[8][4];
        #pragma unroll
        for (int i = 0; i < 8; i++)
            #pragma unroll
            for (int r = 0; r < 4; r++) sacc[i][r] = 0.0f;

        #pragma unroll 4
        for (int ks = 0; ks < 8; ks++) {
            unsigned aq[4];
            ldsm4(aq, qrow_base + (((ks * 8 + lmsel) ^ lsw)) * 4);
            #pragma unroll
            for (int nn = 0; nn < 4; nn++) {
                unsigned bk2[4];
                ldsm4(bk2, kbb + ((nn * 16 + krow) * 64 + ((ks * 8 + ksel) ^ lsw)) * 4);
                mma_f16(sacc[nn * 2 + 0], aq, &bk2[0]);
                mma_f16(sacc[nn * 2 + 1], aq, &bk2[2]);
            }
        }

        float mx0 = -INFINITY, mx1 = -INFINITY;
        #pragma unroll
        for (int nt = 0; nt < 8; nt++) {
            mx0 = fmaxf(mx0, fmaxf(sacc[nt][0], sacc[nt][1]));
            mx1 = fmaxf(mx1, fmaxf(sacc[nt][2], sacc[nt][3]));
        }
        mx0 = fmaxf(mx0, __shfl_xor_sync(0xffffffffu, mx0, 1));
        mx0 = fmaxf(mx0, __shfl_xor_sync(0xffffffffu, mx0, 2));
        mx1 = fmaxf(mx1, __shfl_xor_sync(0xffffffffu, mx1, 1));
        mx1 = fmaxf(mx1, __shfl_xor_sync(0xffffffffu, mx1, 2));
        const float mn0 = fmaxf(m0, mx0 * scale);
        const float mn1 = fmaxf(m1, mx1 * scale);
        const float f0 = __expf(m0 - mn0);
        const float f1 = __expf(m1 - mn1);
        float ps0 = 0.0f, ps1 = 0.0f;
        #pragma unroll
        for (int nt = 0; nt < 8; nt++) {
            sacc[nt][0] = __expf(sacc[nt][0] * scale - mn0);
            sacc[nt][1] = __expf(sacc[nt][1] * scale - mn0);
            sacc[nt][2] = __expf(sacc[nt][2] * scale - mn1);
            sacc[nt][3] = __expf(sacc[nt][3] * scale - mn1);
            ps0 += sacc[nt][0] + sacc[nt][1];
            ps1 += sacc[nt][2] + sacc[nt][3];
        }
        ps0 += __shfl_xor_sync(0xffffffffu, ps0, 1);
        ps0 += __shfl_xor_sync(0xffffffffu, ps0, 2);
        ps1 += __shfl_xor_sync(0xffffffffu, ps1, 1);
        ps1 += __shfl_xor_sync(0xffffffffu, ps1, 2);
        l0 = l0 * f0 + ps0;  m0 = mn0;
        l1 = l1 * f1 + ps1;  m1 = mn1;

        unsigned pa[4][4];
        #pragma unroll
        for (int ks = 0; ks < 4; ks++) {
            __half2 h0 = __floats2half2_rn(sacc[2*ks][0],   sacc[2*ks][1]);
            __half2 h1 = __floats2half2_rn(sacc[2*ks][2],   sacc[2*ks][3]);
            __half2 h2 = __floats2half2_rn(sacc[2*ks+1][0], sacc[2*ks+1][1]);
            __half2 h3 = __floats2half2_rn(sacc[2*ks+1][2], sacc[2*ks+1][3]);
            pa[ks][0] = *(unsigned*)&h0;
            pa[ks][1] = *(unsigned*)&h1;
            pa[ks][2] = *(unsigned*)&h2;
            pa[ks][3] = *(unsigned*)&h3;
        }
        #pragma unroll
        for (int nt = 0; nt < 16; nt++) {
            oacc[nt][0] *= f0; oacc[nt][1] *= f0;
            oacc[nt][2] *= f1; oacc[nt][3] *= f1;
        }

        #pragma unroll
        for (int ks = 0; ks < 4; ks++) {
            #pragma unroll
            for (int nn = 0; nn < 8; nn++) {
                unsigned bv2[4];
                ldsm4t(bv2, vbb + ((ks * 16 + lm15) * 64 + ((nn * 8 + vsel) ^ lsw)) * 4);
                mma_f16(oacc[nn * 2 + 0], pa[ks], &bv2[0]);
                mma_f16(oacc[nn * 2 + 1], pa[ks], &bv2[2]);
            }
        }
        __syncthreads();

        if (it + 2 < SEQ / 64) {
            const int nxt = (it + 2) * 64;
            const uint32_t kd = ATK + (it & 1) * 4096;
            const uint32_t vd = ATV + (it & 1) * 4096;
            #pragma unroll
            for (int p = 0; p < 4; p++) {
                int lin = p * 256 + t;
                int r = lin >> 4, c4 = lin & 15;
                uint32_t swz = ((c4 * 4) ^ ((r & 7) << 2));
                cpa16(sbase + (kd + r * 64 + swz) * 4, kg + (size_t)(nxt + r) * HD + c4 * 8);
                cpa16(sbase + (vd + r * 64 + swz) * 4, vg + (size_t)(nxt + r) * HD + c4 * 8);
            }
            cpa_commit();
        }
    }

    const float il0 = 1.0f / l0;
    const float il1 = 1.0f / l1;
    const int r0 = wid * 16 + g;
    #pragma unroll
    for (int nt = 0; nt < 16; nt++) {
        const int col = nt * 8 + 2 * c;
        size_t base0 = ((size_t)(b * SEQ + q0 + r0)) * HID + h * HD + col;
        size_t base1 = base0 + (size_t)8 * HID;
        __half2 h0 = __floats2half2_rn(oacc[nt][0] * il0, oacc[nt][1] * il0);
        __half2 h1 = __floats2half2_rn(oacc[nt][2] * il1, oacc[nt][3] * il1);
        *(__half2*)(g_atth + base0) = h0;
        *(__half2*)(g_atth + base1) = h1;
    }
}

// ---------------------------------------------------------------------------
extern "C" void kernel_launch(void* const* d_in, const int* in_sizes, int n_in,
                              void* d_out, int out_size) {
    const float* X  = (const float*)d_in[0];
    const float* Wq = (const float*)d_in[1];
    const float* bq = (const float*)d_in[2];
    const float* Wk = (const float*)d_in[3];
    const float* bk = (const float*)d_in[4];
    const float* Wv = (const float*)d_in[5];
    const float* bv = (const float*)d_in[6];
    const float* Wo = (const float*)d_in[7];
    const float* bo = (const float*)d_in[8];
    float* out = (float*)d_out;

    cudaFuncSetAttribute(attn_kernel,
                         cudaFuncAttributeMaxDynamicSharedMemorySize, ASMEM_BYTES);
    cudaFuncSetAttribute(qkv_gemm,
                         cudaFuncAttributeMaxDynamicSharedMemorySize, GSMEM_BYTES);
    cudaFuncSetAttribute(gemm_o,
                         cudaFuncAttributeMaxDynamicSharedMemorySize, GSMEM_BYTES);

    rope_table_kernel<<<(SEQ * HD) / 256, 256>>>();
    cvt_x_kernel<<<(MROWS * HID / 8) / 256, 256>>>(X);
    wtrans_kernel<<<dim3(HID / 32, HID / 32, 4), dim3(32, 8)>>>(Wq, Wk, Wv, Wo);

    dim3 gg(HID / 128, MROWS / 256, 3);
    qkv_gemm<<<gg, 256, GSMEM_BYTES>>>(bq, bk, bv);

    attn_kernel<<<dim3(SEQ / 128, NH, BATCH), 256, ASMEM_BYTES>>>();

    dim3 go(HID / 128, MROWS / 256);
    gemm_o<<<go, 256, GSMEM_BYTES>>>(bo, out);
}